// round 15
// baseline (speedup 1.0000x reference)
#include <cuda_runtime.h>

// ---------------------------------------------------------------------------
// AttentionLayer, 3x/2xTF32 legacy mma.sync.
// R11 algebra (exact):
//   logits = Xq·(Wq Wk^T)·Xs^T + v[s],  v = Xs·(Wk bq)
//   context = (P·Xs)·Wv + bv            (P rows sum to 1)
// NPASS: pre-softmax GEMMs (M, A, S) 3 passes (hh+lh+hl); post-softmax
// (Y, ctx) 2 passes (ahi*bhi + ahi*blo = ahi*b).
// R14 = R13 with BK 16->32 ONLY (R9 inner ordering kept bit-for-bit):
// half the barriers, 2 compute phases of slack per cp.async group.
// ---------------------------------------------------------------------------

#define HID   1024
#define SEQQ  256
#define SEQK  512
#define PAIRS 256
#define MQ    (PAIRS * SEQQ)   // 65536
#define MS    (PAIRS * SEQK)   // 131072

// Scratch (allocation-free rule: __device__ globals) ~1.03 GB
__device__ float g_M [(size_t)HID * HID];        // Wq Wk^T
__device__ float g_A [(size_t)MQ * HID];         // Xq M
__device__ float g_S [(size_t)PAIRS * SEQQ * SEQK];
__device__ float g_Y [(size_t)MQ * HID];         // P Xs
__device__ float g_v [(size_t)PAIRS * SEQK];     // Xs (Wk bq)
__device__ float g_w2[HID];                      // Wk bq

// ---------------------------------------------------------------------------
__device__ __forceinline__ void split_tf32(float x, unsigned &hi, unsigned &lo) {
    unsigned h;
    asm("cvt.rna.tf32.f32 %0, %1;" : "=r"(h) : "f"(x));
    hi = h;
    lo = __float_as_uint(x - __uint_as_float(h));
}

__device__ __forceinline__ unsigned cvt_tf32(float x) {
    unsigned h;
    asm("cvt.rna.tf32.f32 %0, %1;" : "=r"(h) : "f"(x));
    return h;
}

__device__ __forceinline__ void mma_tf32(float c[4], const unsigned a[4], const unsigned b[2]) {
    asm("mma.sync.aligned.m16n8k8.row.col.f32.tf32.tf32.f32 "
        "{%0,%1,%2,%3}, {%4,%5,%6,%7}, {%8,%9}, {%0,%1,%2,%3};"
        : "+f"(c[0]), "+f"(c[1]), "+f"(c[2]), "+f"(c[3])
        : "r"(a[0]), "r"(a[1]), "r"(a[2]), "r"(a[3]), "r"(b[0]), "r"(b[1]));
}

__device__ __forceinline__ void cp16(unsigned smem, const void* g) {
    asm volatile("cp.async.cg.shared.global [%0], [%1], 16;" :: "r"(smem), "l"(g));
}

// ---------------------------------------------------------------------------
// 3x/2xTF32 GEMM: C[M,N] = A[M,K] * B (+bias).
//   TRANSB=false: B is [K,N] row-major.  TRANSB=true: B is [N,K] (C = A B^T).
//   BB: bias batched per z with stride SEQK (the v[s] logits bias).
//   NPASS: 3 = hh+lh+hl (pre-softmax);  2 = ahi*bhi + ahi*blo (post-softmax).
// Block tile 128x128x32, 256 threads (2x4 warps), 2 CTA/SM, 3-stage cp.async.
// smem per stage: As [128][36]; B: TRANSB -> [128][36], else [32][136].
// ---------------------------------------------------------------------------
template <bool TRANSB, bool BIAS, bool BB, int NPASS>
__global__ void __launch_bounds__(256, 2)
gemm3x(const float* __restrict__ A, const float* __restrict__ B,
       const float* __restrict__ bias, float* __restrict__ C,
       int K, int lda, int ldb, int ldc,
       size_t sA, size_t sB, size_t sC)
{
    extern __shared__ float smem[];
    constexpr int ASZ = 128 * 36;
    constexpr int BSZ = TRANSB ? 128 * 36 : 32 * 136;
    constexpr int STG = ASZ + BSZ;                 // floats per stage

    const int tid  = threadIdx.x;
    const int lane = tid & 31;
    const int wm   = (tid >> 5) >> 2;   // 0..1
    const int wn   = (tid >> 5) & 3;    // 0..3
    const int g    = lane >> 2;         // 0..7
    const int tg   = lane & 3;          // 0..3

    const size_t z = blockIdx.z;
    A += z * sA + (size_t)blockIdx.y * 128 * lda;
    if (TRANSB) B += z * sB + (size_t)blockIdx.x * 128 * ldb;
    else        B += z * sB + (size_t)blockIdx.x * 128;
    C += z * sC + (size_t)blockIdx.y * 128 * ldc + (size_t)blockIdx.x * 128;

    // staging coords: 4x cp16 per operand per thread (BK=32 tile)
    const int aR  = tid >> 1, aK0 = (tid & 1) * 16;   // A: 16 consecutive k
    int bY, bX0;
    if (TRANSB) { bY = tid >> 1; bX0 = (tid & 1) * 16; }   // rows=n, k contig
    else        { bY = tid >> 3; bX0 = (tid & 7) * 16; }   // rows=k, n contig

    const unsigned sBase = (unsigned)__cvta_generic_to_shared(smem);
    const unsigned aDst = sBase + (aR * 36 + aK0) * 4;
    const unsigned bDst = sBase + (ASZ + (TRANSB ? bY * 36 + bX0 : bY * 136 + bX0)) * 4;
    constexpr unsigned STG_B = STG * 4;

    auto issue = [&](int t, int s) {
        const float* Ag = A + (size_t)aR * lda + t * 32 + aK0;
        #pragma unroll
        for (int j = 0; j < 4; ++j)
            cp16(aDst + s * STG_B + 16 * j, Ag + 4 * j);
        const float* Bg;
        if (TRANSB) Bg = B + (size_t)bY * ldb + t * 32 + bX0;
        else        Bg = B + (size_t)(t * 32 + bY) * ldb + bX0;
        #pragma unroll
        for (int j = 0; j < 4; ++j)
            cp16(bDst + s * STG_B + 16 * j, Bg + 4 * j);
        asm volatile("cp.async.commit_group;" ::: "memory");
    };

    float acc[4][4][4];
    #pragma unroll
    for (int mi = 0; mi < 4; ++mi)
        #pragma unroll
        for (int ni = 0; ni < 4; ++ni)
            #pragma unroll
            for (int i = 0; i < 4; ++i) acc[mi][ni][i] = 0.f;

    const int nT = K >> 5;

    // prologue: two tiles in flight
    issue(0, 0);
    if (nT > 1) issue(1, 1);

    int buf = 0;
    for (int t = 0; t < nT; ++t) {
        if (t + 1 < nT) asm volatile("cp.async.wait_group 1;" ::: "memory");
        else            asm volatile("cp.async.wait_group 0;" ::: "memory");
        __syncthreads();

        if (t + 2 < nT) issue(t + 2, (buf + 2) % 3);

        const float* A_ = smem + buf * STG;
        const float* B_ = A_ + ASZ;

        #pragma unroll
        for (int kk = 0; kk < 4; ++kk) {
            const int k1 = kk * 8 + tg;

            unsigned bhi[4][2], blo[4][2];
            #pragma unroll
            for (int ni = 0; ni < 4; ++ni) {
                const int n = wn * 32 + ni * 8 + g;
                float b0, b1;
                if (TRANSB) { b0 = B_[n * 36 + k1];  b1 = B_[n * 36 + k1 + 4]; }
                else        { b0 = B_[k1 * 136 + n]; b1 = B_[(k1 + 4) * 136 + n]; }
                split_tf32(b0, bhi[ni][0], blo[ni][0]);
                split_tf32(b1, bhi[ni][1], blo[ni][1]);
            }

            #pragma unroll
            for (int mi = 0; mi < 4; ++mi) {
                const int r = wm * 64 + mi * 16 + g;
                if (NPASS == 3) {
                    unsigned ahi[4], alo[4];
                    split_tf32(A_[r * 36 + k1],           ahi[0], alo[0]);
                    split_tf32(A_[(r + 8) * 36 + k1],     ahi[1], alo[1]);
                    split_tf32(A_[r * 36 + k1 + 4],       ahi[2], alo[2]);
                    split_tf32(A_[(r + 8) * 36 + k1 + 4], ahi[3], alo[3]);
                    #pragma unroll
                    for (int ni = 0; ni < 4; ++ni) {
                        mma_tf32(acc[mi][ni], ahi, bhi[ni]);  // hi*hi
                        mma_tf32(acc[mi][ni], alo, bhi[ni]);  // lo*hi
                        mma_tf32(acc[mi][ni], ahi, blo[ni]);  // hi*lo
                    }
                } else {
                    unsigned ahi[4];
                    ahi[0] = cvt_tf32(A_[r * 36 + k1]);
                    ahi[1] = cvt_tf32(A_[(r + 8) * 36 + k1]);
                    ahi[2] = cvt_tf32(A_[r * 36 + k1 + 4]);
                    ahi[3] = cvt_tf32(A_[(r + 8) * 36 + k1 + 4]);
                    #pragma unroll
                    for (int ni = 0; ni < 4; ++ni) {
                        mma_tf32(acc[mi][ni], ahi, bhi[ni]);  // hi*hi
                        mma_tf32(acc[mi][ni], ahi, blo[ni]);  // hi*lo  (= ahi*b)
                    }
                }
            }
        }

        buf = (buf + 1) % 3;
    }

    // epilogue
    const float* bptr = bias;
    if (BIAS) bptr = bias + (BB ? z * SEQK : (size_t)0) + (size_t)blockIdx.x * 128;
    #pragma unroll
    for (int mi = 0; mi < 4; ++mi) {
        const int r = wm * 64 + mi * 16 + g;
        #pragma unroll
        for (int ni = 0; ni < 4; ++ni) {
            const int cn = wn * 32 + ni * 8 + tg * 2;
            float b0 = 0.f, b1 = 0.f;
            if (BIAS) { b0 = bptr[cn]; b1 = bptr[cn + 1]; }
            float2 v0 = make_float2(acc[mi][ni][0] + b0, acc[mi][ni][1] + b1);
            float2 v1 = make_float2(acc[mi][ni][2] + b0, acc[mi][ni][3] + b1);
            *(float2*)(C + (size_t)r * ldc + cn)       = v0;
            *(float2*)(C + (size_t)(r + 8) * ldc + cn) = v1;
        }
    }
}

// ---------------------------------------------------------------------------
// GEMV: out[r] = dot(Mtx[r, 0:1024], vec), one warp per row.
// ---------------------------------------------------------------------------
__global__ void __launch_bounds__(256)
gemv1024(const float* __restrict__ Mtx, const float* __restrict__ vec,
         float* __restrict__ out, int rows)
{
    const int w    = threadIdx.x >> 5;
    const int lane = threadIdx.x & 31;
    const int r    = blockIdx.x * 8 + w;
    if (r >= rows) return;

    const float4* row = (const float4*)(Mtx + (size_t)r * HID);
    const float4* v4  = (const float4*)vec;
    float s = 0.f;
    #pragma unroll
    for (int i = 0; i < 8; ++i) {
        float4 a = row[lane + 32 * i];
        float4 b = v4[lane + 32 * i];
        s += a.x * b.x + a.y * b.y + a.z * b.z + a.w * b.w;
    }
    #pragma unroll
    for (int o = 16; o; o >>= 1) s += __shfl_xor_sync(0xffffffffu, s, o);
    if (lane == 0) out[r] = s;
}

// ---------------------------------------------------------------------------
// Softmax over rows of S [pairs,256,512] in place + column-sum into scores.
// ---------------------------------------------------------------------------
__global__ void __launch_bounds__(256)
softmax_scores(float* __restrict__ S, float* __restrict__ scores)
{
    const int pair = blockIdx.y;
    const int w    = threadIdx.x >> 5;
    const int lane = threadIdx.x & 31;

    __shared__ float colsum[SEQK];
    for (int i = threadIdx.x; i < SEQK; i += 256) colsum[i] = 0.f;
    __syncthreads();

    float* row = S + (size_t)pair * SEQQ * SEQK + (size_t)(blockIdx.x * 8 + w) * SEQK;

    float v[16];
    #pragma unroll
    for (int i = 0; i < 16; ++i) v[i] = row[lane + 32 * i];

    float m = v[0];
    #pragma unroll
    for (int i = 1; i < 16; ++i) m = fmaxf(m, v[i]);
    #pragma unroll
    for (int o = 16; o; o >>= 1) m = fmaxf(m, __shfl_xor_sync(0xffffffffu, m, o));

    float s = 0.f;
    #pragma unroll
    for (int i = 0; i < 16; ++i) { v[i] = __expf(v[i] - m); s += v[i]; }
    #pragma unroll
    for (int o = 16; o; o >>= 1) s += __shfl_xor_sync(0xffffffffu, s, o);

    const float inv = 1.f / s;
    #pragma unroll
    for (int i = 0; i < 16; ++i) {
        const float p = v[i] * inv;
        row[lane + 32 * i] = p;
        atomicAdd(&colsum[lane + 32 * i], p);
    }
    __syncthreads();
    for (int i = threadIdx.x; i < SEQK; i += 256)
        atomicAdd(&scores[(size_t)pair * SEQK + i], colsum[i]);
}

// ---------------------------------------------------------------------------
// kernel_launch
// inputs: query, source, Wq, bq, Wk, bk, Wv, bv
// output: context [8,32,256,1024] then attention_scores [8,32,512]
// ---------------------------------------------------------------------------
extern "C" void kernel_launch(void* const* d_in, const int* in_sizes, int n_in,
                              void* d_out, int out_size)
{
    const float* query  = (const float*)d_in[0];
    const float* source = (const float*)d_in[1];
    const float* Wq = (const float*)d_in[2];
    const float* bq = (const float*)d_in[3];
    const float* Wk = (const float*)d_in[4];
    // bk unused: its logits contribution is constant per softmax row.
    const float* Wv = (const float*)d_in[6];
    const float* bv = (const float*)d_in[7];

    float* ctx    = (float*)d_out;
    float* scores = ctx + (size_t)PAIRS * SEQQ * HID;

    float *M, *A, *S, *Y, *v, *w2;
    cudaGetSymbolAddress((void**)&M,  g_M);
    cudaGetSymbolAddress((void**)&A,  g_A);
    cudaGetSymbolAddress((void**)&S,  g_S);
    cudaGetSymbolAddress((void**)&Y,  g_Y);
    cudaGetSymbolAddress((void**)&v,  g_v);
    cudaGetSymbolAddress((void**)&w2, g_w2);

    const int SM_T = 3 * (128 * 36 + 128 * 36) * 4;   // 110592 B (TRANSB)
    const int SM_N = 3 * (128 * 36 + 32 * 136) * 4;   // 107520 B

    cudaFuncSetAttribute(gemm3x<true,  false, false, 3>, cudaFuncAttributeMaxDynamicSharedMemorySize, SM_T);
    cudaFuncSetAttribute(gemm3x<true,  true,  true,  3>, cudaFuncAttributeMaxDynamicSharedMemorySize, SM_T);
    cudaFuncSetAttribute(gemm3x<false, false, false, 3>, cudaFuncAttributeMaxDynamicSharedMemorySize, SM_N);
    cudaFuncSetAttribute(gemm3x<false, false, false, 2>, cudaFuncAttributeMaxDynamicSharedMemorySize, SM_N);
    cudaFuncSetAttribute(gemm3x<false, true,  false, 2>, cudaFuncAttributeMaxDynamicSharedMemorySize, SM_N);

    cudaMemsetAsync(scores, 0, (size_t)PAIRS * SEQK * sizeof(float));

    dim3 blk(256);

    // w2 = Wk * bq  (row-dot), then v = Xs * w2 per (pair, s)
    gemv1024<<<HID / 8, 256>>>(Wk, bq, w2, HID);
    gemv1024<<<MS / 8, 256>>>(source, w2, v, MS);

    // M = Wq * Wk^T  [1024,1024]  (3-pass: feeds logits)
    gemm3x<true, false, false, 3><<<dim3(HID / 128, HID / 128, 1), blk, SM_T>>>(
        Wq, Wk, nullptr, M, HID, HID, HID, HID, 0, 0, 0);

    // A = Xq * M  [65536,1024]  (3-pass: feeds logits)
    gemm3x<false, false, false, 3><<<dim3(HID / 128, MQ / 128, 1), blk, SM_N>>>(
        query, M, nullptr, A, HID, HID, HID, HID, 0, 0, 0);

    // logits S = A * Xs^T + v[pair, s]  (3-pass; batched over pairs)
    gemm3x<true, true, true, 3><<<dim3(SEQK / 128, SEQQ / 128, PAIRS), blk, SM_T>>>(
        A, source, v, S, HID, HID, HID, SEQK,
        (size_t)SEQQ * HID, (size_t)SEQK * HID, (size_t)SEQQ * SEQK);

    // softmax (in place -> P) + scores
    softmax_scores<<<dim3(SEQQ / 8, PAIRS), 256>>>(S, scores);

    // Y = P * Xs  (2-pass post-softmax; batched)  [256,1024] per pair
    gemm3x<false, false, false, 2><<<dim3(HID / 128, SEQQ / 128, PAIRS), blk, SM_N>>>(
        S, source, nullptr, Y, SEQK, SEQK, HID, HID,
        (size_t)SEQQ * SEQK, (size_t)SEQK * HID, (size_t)SEQQ * HID);

    // context = Y * Wv + bv  (2-pass post-softmax)  [65536,1024]
    gemm3x<false, true, false, 2><<<dim3(HID / 128, MQ / 128, 1), blk, SM_N>>>(
        Y, Wv, bv, ctx, HID, HID, HID, HID, 0, 0, 0);
}

// round 16
// speedup vs baseline: 1.1852x; 1.1852x over previous
#include <cuda_runtime.h>

// ---------------------------------------------------------------------------
// AttentionLayer, 3x/2xTF32 legacy mma.sync.
// R11 algebra (exact):
//   logits = Xq·(Wq Wk^T)·Xs^T + v[s],  v = Xs·(Wk bq)
//   context = (P·Xs)·Wv + bv            (P rows sum to 1)
// NPASS: pre-softmax GEMMs (M, A, S) 3 passes (hh+lh+hl); post-softmax
// (Y, ctx) 2 passes (ahi*bhi + ahi*blo = ahi*b).
// R15 = R13 core (BK=16 — BK=32 falsified in isolation in R14) with
// pipeline depth 3 -> 4 (each cp.async group gets 3 compute phases of slack).
// ---------------------------------------------------------------------------

#define HID   1024
#define SEQQ  256
#define SEQK  512
#define PAIRS 256
#define MQ    (PAIRS * SEQQ)   // 65536
#define MS    (PAIRS * SEQK)   // 131072

// Scratch (allocation-free rule: __device__ globals) ~1.03 GB
__device__ float g_M [(size_t)HID * HID];        // Wq Wk^T
__device__ float g_A [(size_t)MQ * HID];         // Xq M
__device__ float g_S [(size_t)PAIRS * SEQQ * SEQK];
__device__ float g_Y [(size_t)MQ * HID];         // P Xs
__device__ float g_v [(size_t)PAIRS * SEQK];     // Xs (Wk bq)
__device__ float g_w2[HID];                      // Wk bq

// ---------------------------------------------------------------------------
__device__ __forceinline__ void split_tf32(float x, unsigned &hi, unsigned &lo) {
    unsigned h;
    asm("cvt.rna.tf32.f32 %0, %1;" : "=r"(h) : "f"(x));
    hi = h;
    lo = __float_as_uint(x - __uint_as_float(h));
}

__device__ __forceinline__ unsigned cvt_tf32(float x) {
    unsigned h;
    asm("cvt.rna.tf32.f32 %0, %1;" : "=r"(h) : "f"(x));
    return h;
}

__device__ __forceinline__ void mma_tf32(float c[4], const unsigned a[4], const unsigned b[2]) {
    asm("mma.sync.aligned.m16n8k8.row.col.f32.tf32.tf32.f32 "
        "{%0,%1,%2,%3}, {%4,%5,%6,%7}, {%8,%9}, {%0,%1,%2,%3};"
        : "+f"(c[0]), "+f"(c[1]), "+f"(c[2]), "+f"(c[3])
        : "r"(a[0]), "r"(a[1]), "r"(a[2]), "r"(a[3]), "r"(b[0]), "r"(b[1]));
}

__device__ __forceinline__ void cp16(unsigned smem, const void* g) {
    asm volatile("cp.async.cg.shared.global [%0], [%1], 16;" :: "r"(smem), "l"(g));
}

// ---------------------------------------------------------------------------
// 3x/2xTF32 GEMM: C[M,N] = A[M,K] * B (+bias).
//   TRANSB=false: B is [K,N] row-major.  TRANSB=true: B is [N,K] (C = A B^T).
//   BB: bias batched per z with stride SEQK (the v[s] logits bias).
//   NPASS: 3 = hh+lh+hl (pre-softmax);  2 = ahi*bhi + ahi*blo (post-softmax).
// Block tile 128x128x16, 256 threads (2x4 warps), 2 CTA/SM, 4-stage cp.async.
// smem per stage: As [128][20]; B: TRANSB -> [128][20], else [16][136].
// ---------------------------------------------------------------------------
template <bool TRANSB, bool BIAS, bool BB, int NPASS>
__global__ void __launch_bounds__(256, 2)
gemm3x(const float* __restrict__ A, const float* __restrict__ B,
       const float* __restrict__ bias, float* __restrict__ C,
       int K, int lda, int ldb, int ldc,
       size_t sA, size_t sB, size_t sC)
{
    extern __shared__ float smem[];
    constexpr int ASZ = 128 * 20;
    constexpr int BSZ = TRANSB ? 128 * 20 : 16 * 136;
    constexpr int STG = ASZ + BSZ;                 // floats per stage

    const int tid  = threadIdx.x;
    const int lane = tid & 31;
    const int wm   = (tid >> 5) >> 2;   // 0..1
    const int wn   = (tid >> 5) & 3;    // 0..3
    const int g    = lane >> 2;         // 0..7
    const int tg   = lane & 3;          // 0..3

    const size_t z = blockIdx.z;
    A += z * sA + (size_t)blockIdx.y * 128 * lda;
    if (TRANSB) B += z * sB + (size_t)blockIdx.x * 128 * ldb;
    else        B += z * sB + (size_t)blockIdx.x * 128;
    C += z * sC + (size_t)blockIdx.y * 128 * ldc + (size_t)blockIdx.x * 128;

    // staging coordinates (two 16B cp.async per operand per thread)
    const int aR0 = tid >> 2, aK0 = (tid & 3) * 4;   // k-contiguous
    const int aR1 = aR0 + 64;
    int bY0, bX0, bY1;
    if (TRANSB) { bY0 = tid >> 2;  bX0 = (tid & 3) * 4;  bY1 = bY0 + 64; }  // rows=n, k contig
    else        { bY0 = tid >> 5;  bX0 = (tid & 31) * 4; bY1 = bY0 + 8;  }  // rows=k, n contig

    const unsigned sBase = (unsigned)__cvta_generic_to_shared(smem);
    const unsigned aDst0 = sBase + (aR0 * 20 + aK0) * 4;
    const unsigned aDst1 = sBase + (aR1 * 20 + aK0) * 4;
    const unsigned bOff  = ASZ * 4;
    const unsigned bDst0 = sBase + bOff + (TRANSB ? (bY0 * 20 + bX0) : (bY0 * 136 + bX0)) * 4;
    const unsigned bDst1 = sBase + bOff + (TRANSB ? (bY1 * 20 + bX0) : (bY1 * 136 + bX0)) * 4;
    constexpr unsigned STG_B = STG * 4;

    auto issue = [&](int t, int s) {
        const float* At = A + (size_t)t * 16;
        cp16(aDst0 + s * STG_B, At + (size_t)aR0 * lda + aK0);
        cp16(aDst1 + s * STG_B, At + (size_t)aR1 * lda + aK0);
        if (TRANSB) {
            const float* Bt = B + (size_t)t * 16;
            cp16(bDst0 + s * STG_B, Bt + (size_t)bY0 * ldb + bX0);
            cp16(bDst1 + s * STG_B, Bt + (size_t)bY1 * ldb + bX0);
        } else {
            const float* Bt = B + (size_t)t * 16 * ldb;
            cp16(bDst0 + s * STG_B, Bt + (size_t)bY0 * ldb + bX0);
            cp16(bDst1 + s * STG_B, Bt + (size_t)bY1 * ldb + bX0);
        }
        asm volatile("cp.async.commit_group;" ::: "memory");
    };

    float acc[4][4][4];
    #pragma unroll
    for (int mi = 0; mi < 4; ++mi)
        #pragma unroll
        for (int ni = 0; ni < 4; ++ni)
            #pragma unroll
            for (int i = 0; i < 4; ++i) acc[mi][ni][i] = 0.f;

    const int nT = K >> 4;

    // prologue: three tiles in flight (4-stage pipeline)
    issue(0, 0);
    if (nT > 1) issue(1, 1);
    if (nT > 2) issue(2, 2);

    int buf = 0;
    for (int t = 0; t < nT; ++t) {
        // newer groups in flight = min(nT-1, t+2) - t; wait for tile t exactly
        if (t + 2 < nT)      asm volatile("cp.async.wait_group 2;" ::: "memory");
        else if (t + 1 < nT) asm volatile("cp.async.wait_group 1;" ::: "memory");
        else                 asm volatile("cp.async.wait_group 0;" ::: "memory");
        __syncthreads();   // tile t visible to all; all warps done with buf we overwrite

        if (t + 3 < nT) issue(t + 3, (buf + 3) & 3);

        const float* A_ = smem + buf * STG;
        const float* B_ = A_ + ASZ;

        #pragma unroll
        for (int kk = 0; kk < 2; ++kk) {
            const int k1 = kk * 8 + tg;

            unsigned bhi[4][2], blo[4][2];
            #pragma unroll
            for (int ni = 0; ni < 4; ++ni) {
                const int n = wn * 32 + ni * 8 + g;
                float b0, b1;
                if (TRANSB) { b0 = B_[n * 20 + k1];  b1 = B_[n * 20 + k1 + 4]; }
                else        { b0 = B_[k1 * 136 + n]; b1 = B_[(k1 + 4) * 136 + n]; }
                split_tf32(b0, bhi[ni][0], blo[ni][0]);
                split_tf32(b1, bhi[ni][1], blo[ni][1]);
            }

            #pragma unroll
            for (int mi = 0; mi < 4; ++mi) {
                const int r = wm * 64 + mi * 16 + g;
                if (NPASS == 3) {
                    unsigned ahi[4], alo[4];
                    split_tf32(A_[r * 20 + k1],           ahi[0], alo[0]);
                    split_tf32(A_[(r + 8) * 20 + k1],     ahi[1], alo[1]);
                    split_tf32(A_[r * 20 + k1 + 4],       ahi[2], alo[2]);
                    split_tf32(A_[(r + 8) * 20 + k1 + 4], ahi[3], alo[3]);
                    #pragma unroll
                    for (int ni = 0; ni < 4; ++ni) {
                        mma_tf32(acc[mi][ni], ahi, bhi[ni]);  // hi*hi
                        mma_tf32(acc[mi][ni], alo, bhi[ni]);  // lo*hi
                        mma_tf32(acc[mi][ni], ahi, blo[ni]);  // hi*lo
                    }
                } else {
                    unsigned ahi[4];
                    ahi[0] = cvt_tf32(A_[r * 20 + k1]);
                    ahi[1] = cvt_tf32(A_[(r + 8) * 20 + k1]);
                    ahi[2] = cvt_tf32(A_[r * 20 + k1 + 4]);
                    ahi[3] = cvt_tf32(A_[(r + 8) * 20 + k1 + 4]);
                    #pragma unroll
                    for (int ni = 0; ni < 4; ++ni) {
                        mma_tf32(acc[mi][ni], ahi, bhi[ni]);  // hi*hi
                        mma_tf32(acc[mi][ni], ahi, blo[ni]);  // hi*lo  (= ahi*b)
                    }
                }
            }
        }

        buf = (buf + 1) & 3;
    }

    // epilogue
    const float* bptr = bias;
    if (BIAS) bptr = bias + (BB ? z * SEQK : (size_t)0) + (size_t)blockIdx.x * 128;
    #pragma unroll
    for (int mi = 0; mi < 4; ++mi) {
        const int r = wm * 64 + mi * 16 + g;
        #pragma unroll
        for (int ni = 0; ni < 4; ++ni) {
            const int cn = wn * 32 + ni * 8 + tg * 2;
            float b0 = 0.f, b1 = 0.f;
            if (BIAS) { b0 = bptr[cn]; b1 = bptr[cn + 1]; }
            float2 v0 = make_float2(acc[mi][ni][0] + b0, acc[mi][ni][1] + b1);
            float2 v1 = make_float2(acc[mi][ni][2] + b0, acc[mi][ni][3] + b1);
            *(float2*)(C + (size_t)r * ldc + cn)       = v0;
            *(float2*)(C + (size_t)(r + 8) * ldc + cn) = v1;
        }
    }
}

// ---------------------------------------------------------------------------
// GEMV: out[r] = dot(Mtx[r, 0:1024], vec), one warp per row.
// ---------------------------------------------------------------------------
__global__ void __launch_bounds__(256)
gemv1024(const float* __restrict__ Mtx, const float* __restrict__ vec,
         float* __restrict__ out, int rows)
{
    const int w    = threadIdx.x >> 5;
    const int lane = threadIdx.x & 31;
    const int r    = blockIdx.x * 8 + w;
    if (r >= rows) return;

    const float4* row = (const float4*)(Mtx + (size_t)r * HID);
    const float4* v4  = (const float4*)vec;
    float s = 0.f;
    #pragma unroll
    for (int i = 0; i < 8; ++i) {
        float4 a = row[lane + 32 * i];
        float4 b = v4[lane + 32 * i];
        s += a.x * b.x + a.y * b.y + a.z * b.z + a.w * b.w;
    }
    #pragma unroll
    for (int o = 16; o; o >>= 1) s += __shfl_xor_sync(0xffffffffu, s, o);
    if (lane == 0) out[r] = s;
}

// ---------------------------------------------------------------------------
// Softmax over rows of S [pairs,256,512] in place + column-sum into scores.
// ---------------------------------------------------------------------------
__global__ void __launch_bounds__(256)
softmax_scores(float* __restrict__ S, float* __restrict__ scores)
{
    const int pair = blockIdx.y;
    const int w    = threadIdx.x >> 5;
    const int lane = threadIdx.x & 31;

    __shared__ float colsum[SEQK];
    for (int i = threadIdx.x; i < SEQK; i += 256) colsum[i] = 0.f;
    __syncthreads();

    float* row = S + (size_t)pair * SEQQ * SEQK + (size_t)(blockIdx.x * 8 + w) * SEQK;

    float v[16];
    #pragma unroll
    for (int i = 0; i < 16; ++i) v[i] = row[lane + 32 * i];

    float m = v[0];
    #pragma unroll
    for (int i = 1; i < 16; ++i) m = fmaxf(m, v[i]);
    #pragma unroll
    for (int o = 16; o; o >>= 1) m = fmaxf(m, __shfl_xor_sync(0xffffffffu, m, o));

    float s = 0.f;
    #pragma unroll
    for (int i = 0; i < 16; ++i) { v[i] = __expf(v[i] - m); s += v[i]; }
    #pragma unroll
    for (int o = 16; o; o >>= 1) s += __shfl_xor_sync(0xffffffffu, s, o);

    const float inv = 1.f / s;
    #pragma unroll
    for (int i = 0; i < 16; ++i) {
        const float p = v[i] * inv;
        row[lane + 32 * i] = p;
        atomicAdd(&colsum[lane + 32 * i], p);
    }
    __syncthreads();
    for (int i = threadIdx.x; i < SEQK; i += 256)
        atomicAdd(&scores[(size_t)pair * SEQK + i], colsum[i]);
}

// ---------------------------------------------------------------------------
// kernel_launch
// inputs: query, source, Wq, bq, Wk, bk, Wv, bv
// output: context [8,32,256,1024] then attention_scores [8,32,512]
// ---------------------------------------------------------------------------
extern "C" void kernel_launch(void* const* d_in, const int* in_sizes, int n_in,
                              void* d_out, int out_size)
{
    const float* query  = (const float*)d_in[0];
    const float* source = (const float*)d_in[1];
    const float* Wq = (const float*)d_in[2];
    const float* bq = (const float*)d_in[3];
    const float* Wk = (const float*)d_in[4];
    // bk unused: its logits contribution is constant per softmax row.
    const float* Wv = (const float*)d_in[6];
    const float* bv = (const float*)d_in[7];

    float* ctx    = (float*)d_out;
    float* scores = ctx + (size_t)PAIRS * SEQQ * HID;

    float *M, *A, *S, *Y, *v, *w2;
    cudaGetSymbolAddress((void**)&M,  g_M);
    cudaGetSymbolAddress((void**)&A,  g_A);
    cudaGetSymbolAddress((void**)&S,  g_S);
    cudaGetSymbolAddress((void**)&Y,  g_Y);
    cudaGetSymbolAddress((void**)&v,  g_v);
    cudaGetSymbolAddress((void**)&w2, g_w2);

    const int SM_T = 4 * (128 * 20 + 128 * 20) * 4;   // 81920 B (TRANSB)
    const int SM_N = 4 * (128 * 20 + 16 * 136) * 4;   // 75776 B

    cudaFuncSetAttribute(gemm3x<true,  false, false, 3>, cudaFuncAttributeMaxDynamicSharedMemorySize, SM_T);
    cudaFuncSetAttribute(gemm3x<true,  true,  true,  3>, cudaFuncAttributeMaxDynamicSharedMemorySize, SM_T);
    cudaFuncSetAttribute(gemm3x<false, false, false, 3>, cudaFuncAttributeMaxDynamicSharedMemorySize, SM_N);
    cudaFuncSetAttribute(gemm3x<false, false, false, 2>, cudaFuncAttributeMaxDynamicSharedMemorySize, SM_N);
    cudaFuncSetAttribute(gemm3x<false, true,  false, 2>, cudaFuncAttributeMaxDynamicSharedMemorySize, SM_N);

    cudaMemsetAsync(scores, 0, (size_t)PAIRS * SEQK * sizeof(float));

    dim3 blk(256);

    // w2 = Wk * bq  (row-dot), then v = Xs * w2 per (pair, s)
    gemv1024<<<HID / 8, 256>>>(Wk, bq, w2, HID);
    gemv1024<<<MS / 8, 256>>>(source, w2, v, MS);

    // M = Wq * Wk^T  [1024,1024]  (3-pass: feeds logits)
    gemm3x<true, false, false, 3><<<dim3(HID / 128, HID / 128, 1), blk, SM_T>>>(
        Wq, Wk, nullptr, M, HID, HID, HID, HID, 0, 0, 0);

    // A = Xq * M  [65536,1024]  (3-pass: feeds logits)
    gemm3x<false, false, false, 3><<<dim3(HID / 128, MQ / 128, 1), blk, SM_N>>>(
        query, M, nullptr, A, HID, HID, HID, HID, 0, 0, 0);

    // logits S = A * Xs^T + v[pair, s]  (3-pass; batched over pairs)
    gemm3x<true, true, true, 3><<<dim3(SEQK / 128, SEQQ / 128, PAIRS), blk, SM_T>>>(
        A, source, v, S, HID, HID, HID, SEQK,
        (size_t)SEQQ * HID, (size_t)SEQK * HID, (size_t)SEQQ * SEQK);

    // softmax (in place -> P) + scores
    softmax_scores<<<dim3(SEQQ / 8, PAIRS), 256>>>(S, scores);

    // Y = P * Xs  (2-pass post-softmax; batched)  [256,1024] per pair
    gemm3x<false, false, false, 2><<<dim3(HID / 128, SEQQ / 128, PAIRS), blk, SM_N>>>(
        S, source, nullptr, Y, SEQK, SEQK, HID, HID,
        (size_t)SEQQ * SEQK, (size_t)SEQK * HID, (size_t)SEQQ * HID);

    // context = Y * Wv + bv  (2-pass post-softmax)  [65536,1024]
    gemm3x<false, true, false, 2><<<dim3(HID / 128, MQ / 128, 1), blk, SM_N>>>(
        Y, Wv, bv, ctx, HID, HID, HID, HID, 0, 0, 0);
}

// round 17
// speedup vs baseline: 1.3247x; 1.1177x over previous
#include <cuda_runtime.h>

// ---------------------------------------------------------------------------
// AttentionLayer. R11 algebra (exact):
//   logits = Xq·(Wq Wk^T)·Xs^T + v[s],  v = Xs·(Wk bq)
//   context = (P·Xs)·Wv + bv            (P rows sum to 1)
// GEMM precision plan:
//   M, S      : tf32 3-pass (hh+lh+hl)          [feeds logits, max precision]
//   A = Xq·M  : bf16 3-pass (hh+lh+hl), 2x MAC rate  <- R16 change
//   Y, ctx    : tf32 2-pass (ahi*b)
// Schedule: R15 core (BK=16, 2 CTA/SM, 4-stage cp.async).
// ---------------------------------------------------------------------------

#define HID   1024
#define SEQQ  256
#define SEQK  512
#define PAIRS 256
#define MQ    (PAIRS * SEQQ)   // 65536
#define MS    (PAIRS * SEQK)   // 131072

// Scratch (allocation-free rule: __device__ globals) ~1.03 GB
__device__ float g_M [(size_t)HID * HID];        // Wq Wk^T
__device__ float g_A [(size_t)MQ * HID];         // Xq M
__device__ float g_S [(size_t)PAIRS * SEQQ * SEQK];
__device__ float g_Y [(size_t)MQ * HID];         // P Xs
__device__ float g_v [(size_t)PAIRS * SEQK];     // Xs (Wk bq)
__device__ float g_w2[HID];                      // Wk bq

// ---------------------------------------------------------------------------
__device__ __forceinline__ void split_tf32(float x, unsigned &hi, unsigned &lo) {
    unsigned h;
    asm("cvt.rna.tf32.f32 %0, %1;" : "=r"(h) : "f"(x));
    hi = h;
    lo = __float_as_uint(x - __uint_as_float(h));
}

__device__ __forceinline__ unsigned cvt_tf32(float x) {
    unsigned h;
    asm("cvt.rna.tf32.f32 %0, %1;" : "=r"(h) : "f"(x));
    return h;
}

__device__ __forceinline__ void mma_tf32(float c[4], const unsigned a[4], const unsigned b[2]) {
    asm("mma.sync.aligned.m16n8k8.row.col.f32.tf32.tf32.f32 "
        "{%0,%1,%2,%3}, {%4,%5,%6,%7}, {%8,%9}, {%0,%1,%2,%3};"
        : "+f"(c[0]), "+f"(c[1]), "+f"(c[2]), "+f"(c[3])
        : "r"(a[0]), "r"(a[1]), "r"(a[2]), "r"(a[3]), "r"(b[0]), "r"(b[1]));
}

// pack two f32 into bf16x2 {x1:hi16, x0:lo16} and exact residuals.
__device__ __forceinline__ void split_bf16x2(float x0, float x1, unsigned &hi, unsigned &lo) {
    unsigned h;
    asm("cvt.rn.bf16x2.f32 %0, %1, %2;" : "=r"(h) : "f"(x1), "f"(x0));
    float h0 = __uint_as_float(h << 16);
    float h1 = __uint_as_float(h & 0xFFFF0000u);
    float l0 = x0 - h0, l1 = x1 - h1;
    unsigned l;
    asm("cvt.rn.bf16x2.f32 %0, %1, %2;" : "=r"(l) : "f"(l1), "f"(l0));
    hi = h; lo = l;
}

__device__ __forceinline__ void mma_bf16(float c[4], const unsigned a[4], const unsigned b[2]) {
    asm("mma.sync.aligned.m16n8k16.row.col.f32.bf16.bf16.f32 "
        "{%0,%1,%2,%3}, {%4,%5,%6,%7}, {%8,%9}, {%0,%1,%2,%3};"
        : "+f"(c[0]), "+f"(c[1]), "+f"(c[2]), "+f"(c[3])
        : "r"(a[0]), "r"(a[1]), "r"(a[2]), "r"(a[3]), "r"(b[0]), "r"(b[1]));
}

__device__ __forceinline__ void cp16(unsigned smem, const void* g) {
    asm volatile("cp.async.cg.shared.global [%0], [%1], 16;" :: "r"(smem), "l"(g));
}

// ---------------------------------------------------------------------------
// tf32 GEMM (R15 core): C[M,N] = A[M,K] * B (+bias).
//   TRANSB=false: B is [K,N] row-major.  TRANSB=true: B is [N,K] (C = A B^T).
//   BB: bias batched per z with stride SEQK.  NPASS: 3 or 2.
// Block tile 128x128x16, 256 threads, 2 CTA/SM, 4-stage cp.async.
// ---------------------------------------------------------------------------
template <bool TRANSB, bool BIAS, bool BB, int NPASS>
__global__ void __launch_bounds__(256, 2)
gemm3x(const float* __restrict__ A, const float* __restrict__ B,
       const float* __restrict__ bias, float* __restrict__ C,
       int K, int lda, int ldb, int ldc,
       size_t sA, size_t sB, size_t sC)
{
    extern __shared__ float smem[];
    constexpr int ASZ = 128 * 20;
    constexpr int BSZ = TRANSB ? 128 * 20 : 16 * 136;
    constexpr int STG = ASZ + BSZ;

    const int tid  = threadIdx.x;
    const int lane = tid & 31;
    const int wm   = (tid >> 5) >> 2;
    const int wn   = (tid >> 5) & 3;
    const int g    = lane >> 2;
    const int tg   = lane & 3;

    const size_t z = blockIdx.z;
    A += z * sA + (size_t)blockIdx.y * 128 * lda;
    if (TRANSB) B += z * sB + (size_t)blockIdx.x * 128 * ldb;
    else        B += z * sB + (size_t)blockIdx.x * 128;
    C += z * sC + (size_t)blockIdx.y * 128 * ldc + (size_t)blockIdx.x * 128;

    const int aR0 = tid >> 2, aK0 = (tid & 3) * 4;
    const int aR1 = aR0 + 64;
    int bY0, bX0, bY1;
    if (TRANSB) { bY0 = tid >> 2;  bX0 = (tid & 3) * 4;  bY1 = bY0 + 64; }
    else        { bY0 = tid >> 5;  bX0 = (tid & 31) * 4; bY1 = bY0 + 8;  }

    const unsigned sBase = (unsigned)__cvta_generic_to_shared(smem);
    const unsigned aDst0 = sBase + (aR0 * 20 + aK0) * 4;
    const unsigned aDst1 = sBase + (aR1 * 20 + aK0) * 4;
    const unsigned bOff  = ASZ * 4;
    const unsigned bDst0 = sBase + bOff + (TRANSB ? (bY0 * 20 + bX0) : (bY0 * 136 + bX0)) * 4;
    const unsigned bDst1 = sBase + bOff + (TRANSB ? (bY1 * 20 + bX0) : (bY1 * 136 + bX0)) * 4;
    constexpr unsigned STG_B = STG * 4;

    auto issue = [&](int t, int s) {
        const float* At = A + (size_t)t * 16;
        cp16(aDst0 + s * STG_B, At + (size_t)aR0 * lda + aK0);
        cp16(aDst1 + s * STG_B, At + (size_t)aR1 * lda + aK0);
        if (TRANSB) {
            const float* Bt = B + (size_t)t * 16;
            cp16(bDst0 + s * STG_B, Bt + (size_t)bY0 * ldb + bX0);
            cp16(bDst1 + s * STG_B, Bt + (size_t)bY1 * ldb + bX0);
        } else {
            const float* Bt = B + (size_t)t * 16 * ldb;
            cp16(bDst0 + s * STG_B, Bt + (size_t)bY0 * ldb + bX0);
            cp16(bDst1 + s * STG_B, Bt + (size_t)bY1 * ldb + bX0);
        }
        asm volatile("cp.async.commit_group;" ::: "memory");
    };

    float acc[4][4][4];
    #pragma unroll
    for (int mi = 0; mi < 4; ++mi)
        #pragma unroll
        for (int ni = 0; ni < 4; ++ni)
            #pragma unroll
            for (int i = 0; i < 4; ++i) acc[mi][ni][i] = 0.f;

    const int nT = K >> 4;

    issue(0, 0);
    if (nT > 1) issue(1, 1);
    if (nT > 2) issue(2, 2);

    int buf = 0;
    for (int t = 0; t < nT; ++t) {
        if (t + 2 < nT)      asm volatile("cp.async.wait_group 2;" ::: "memory");
        else if (t + 1 < nT) asm volatile("cp.async.wait_group 1;" ::: "memory");
        else                 asm volatile("cp.async.wait_group 0;" ::: "memory");
        __syncthreads();

        if (t + 3 < nT) issue(t + 3, (buf + 3) & 3);

        const float* A_ = smem + buf * STG;
        const float* B_ = A_ + ASZ;

        #pragma unroll
        for (int kk = 0; kk < 2; ++kk) {
            const int k1 = kk * 8 + tg;

            unsigned bhi[4][2], blo[4][2];
            #pragma unroll
            for (int ni = 0; ni < 4; ++ni) {
                const int n = wn * 32 + ni * 8 + g;
                float b0, b1;
                if (TRANSB) { b0 = B_[n * 20 + k1];  b1 = B_[n * 20 + k1 + 4]; }
                else        { b0 = B_[k1 * 136 + n]; b1 = B_[(k1 + 4) * 136 + n]; }
                split_tf32(b0, bhi[ni][0], blo[ni][0]);
                split_tf32(b1, bhi[ni][1], blo[ni][1]);
            }

            #pragma unroll
            for (int mi = 0; mi < 4; ++mi) {
                const int r = wm * 64 + mi * 16 + g;
                if (NPASS == 3) {
                    unsigned ahi[4], alo[4];
                    split_tf32(A_[r * 20 + k1],           ahi[0], alo[0]);
                    split_tf32(A_[(r + 8) * 20 + k1],     ahi[1], alo[1]);
                    split_tf32(A_[r * 20 + k1 + 4],       ahi[2], alo[2]);
                    split_tf32(A_[(r + 8) * 20 + k1 + 4], ahi[3], alo[3]);
                    #pragma unroll
                    for (int ni = 0; ni < 4; ++ni) {
                        mma_tf32(acc[mi][ni], ahi, bhi[ni]);
                        mma_tf32(acc[mi][ni], alo, bhi[ni]);
                        mma_tf32(acc[mi][ni], ahi, blo[ni]);
                    }
                } else {
                    unsigned ahi[4];
                    ahi[0] = cvt_tf32(A_[r * 20 + k1]);
                    ahi[1] = cvt_tf32(A_[(r + 8) * 20 + k1]);
                    ahi[2] = cvt_tf32(A_[r * 20 + k1 + 4]);
                    ahi[3] = cvt_tf32(A_[(r + 8) * 20 + k1 + 4]);
                    #pragma unroll
                    for (int ni = 0; ni < 4; ++ni) {
                        mma_tf32(acc[mi][ni], ahi, bhi[ni]);
                        mma_tf32(acc[mi][ni], ahi, blo[ni]);
                    }
                }
            }
        }

        buf = (buf + 1) & 3;
    }

    const float* bptr = bias;
    if (BIAS) bptr = bias + (BB ? z * SEQK : (size_t)0) + (size_t)blockIdx.x * 128;
    #pragma unroll
    for (int mi = 0; mi < 4; ++mi) {
        const int r = wm * 64 + mi * 16 + g;
        #pragma unroll
        for (int ni = 0; ni < 4; ++ni) {
            const int cn = wn * 32 + ni * 8 + tg * 2;
            float b0 = 0.f, b1 = 0.f;
            if (BIAS) { b0 = bptr[cn]; b1 = bptr[cn + 1]; }
            float2 v0 = make_float2(acc[mi][ni][0] + b0, acc[mi][ni][1] + b1);
            float2 v1 = make_float2(acc[mi][ni][2] + b0, acc[mi][ni][3] + b1);
            *(float2*)(C + (size_t)r * ldc + cn)       = v0;
            *(float2*)(C + (size_t)(r + 8) * ldc + cn) = v1;
        }
    }
}

// ---------------------------------------------------------------------------
// bf16x3 GEMM (A-GEMM only): C[M,N] = A[M,K] * B[K,N], no bias, no batch.
// m16n8k16 bf16 MMA = 2x MAC rate; 3 passes hh+lh+hl.
// Same tiles / staging / 4-stage pipeline as gemm3x<false,...>.
// ---------------------------------------------------------------------------
__global__ void __launch_bounds__(256, 2)
gemmbf(const float* __restrict__ A, const float* __restrict__ B,
       float* __restrict__ C, int K, int lda, int ldb, int ldc)
{
    extern __shared__ float smem[];
    constexpr int ASZ = 128 * 20;
    constexpr int BSZ = 16 * 136;
    constexpr int STG = ASZ + BSZ;

    const int tid  = threadIdx.x;
    const int lane = tid & 31;
    const int wm   = (tid >> 5) >> 2;
    const int wn   = (tid >> 5) & 3;
    const int g    = lane >> 2;
    const int tg   = lane & 3;

    A += (size_t)blockIdx.y * 128 * lda;
    B += (size_t)blockIdx.x * 128;
    C += (size_t)blockIdx.y * 128 * ldc + (size_t)blockIdx.x * 128;

    const int aR0 = tid >> 2, aK0 = (tid & 3) * 4;
    const int aR1 = aR0 + 64;
    const int bY0 = tid >> 5, bX0 = (tid & 31) * 4, bY1 = bY0 + 8;

    const unsigned sBase = (unsigned)__cvta_generic_to_shared(smem);
    const unsigned aDst0 = sBase + (aR0 * 20 + aK0) * 4;
    const unsigned aDst1 = sBase + (aR1 * 20 + aK0) * 4;
    const unsigned bDst0 = sBase + (ASZ + bY0 * 136 + bX0) * 4;
    const unsigned bDst1 = sBase + (ASZ + bY1 * 136 + bX0) * 4;
    constexpr unsigned STG_B = STG * 4;

    auto issue = [&](int t, int s) {
        const float* At = A + (size_t)t * 16;
        cp16(aDst0 + s * STG_B, At + (size_t)aR0 * lda + aK0);
        cp16(aDst1 + s * STG_B, At + (size_t)aR1 * lda + aK0);
        const float* Bt = B + (size_t)t * 16 * ldb;
        cp16(bDst0 + s * STG_B, Bt + (size_t)bY0 * ldb + bX0);
        cp16(bDst1 + s * STG_B, Bt + (size_t)bY1 * ldb + bX0);
        asm volatile("cp.async.commit_group;" ::: "memory");
    };

    float acc[4][4][4];
    #pragma unroll
    for (int mi = 0; mi < 4; ++mi)
        #pragma unroll
        for (int ni = 0; ni < 4; ++ni)
            #pragma unroll
            for (int i = 0; i < 4; ++i) acc[mi][ni][i] = 0.f;

    const int nT = K >> 4;

    issue(0, 0);
    if (nT > 1) issue(1, 1);
    if (nT > 2) issue(2, 2);

    const int k0 = 2 * tg;   // fragment k base: {k0,k0+1,k0+8,k0+9}

    int buf = 0;
    for (int t = 0; t < nT; ++t) {
        if (t + 2 < nT)      asm volatile("cp.async.wait_group 2;" ::: "memory");
        else if (t + 1 < nT) asm volatile("cp.async.wait_group 1;" ::: "memory");
        else                 asm volatile("cp.async.wait_group 0;" ::: "memory");
        __syncthreads();

        if (t + 3 < nT) issue(t + 3, (buf + 3) & 3);

        const float* A_ = smem + buf * STG;
        const float* B_ = A_ + ASZ;

        // B fragments: b reg0 = {B[k0][n], B[k0+1][n]}, reg1 = {B[k0+8][n], ...}
        unsigned bhi[4][2], blo[4][2];
        #pragma unroll
        for (int ni = 0; ni < 4; ++ni) {
            const int n = wn * 32 + ni * 8 + g;
            float x0 = B_[k0 * 136 + n],       x1 = B_[(k0 + 1) * 136 + n];
            float x2 = B_[(k0 + 8) * 136 + n], x3 = B_[(k0 + 9) * 136 + n];
            split_bf16x2(x0, x1, bhi[ni][0], blo[ni][0]);
            split_bf16x2(x2, x3, bhi[ni][1], blo[ni][1]);
        }

        #pragma unroll
        for (int mi = 0; mi < 4; ++mi) {
            const int r = wm * 64 + mi * 16 + g;
            // a reg0={A[r][k0,k0+1]}, reg1={A[r+8][..]}, reg2={A[r][k0+8,k0+9]}, reg3={A[r+8][..]}
            unsigned ahi[4], alo[4];
            split_bf16x2(A_[r * 20 + k0],           A_[r * 20 + k0 + 1],           ahi[0], alo[0]);
            split_bf16x2(A_[(r + 8) * 20 + k0],     A_[(r + 8) * 20 + k0 + 1],     ahi[1], alo[1]);
            split_bf16x2(A_[r * 20 + k0 + 8],       A_[r * 20 + k0 + 9],           ahi[2], alo[2]);
            split_bf16x2(A_[(r + 8) * 20 + k0 + 8], A_[(r + 8) * 20 + k0 + 9],     ahi[3], alo[3]);
            #pragma unroll
            for (int ni = 0; ni < 4; ++ni) {
                mma_bf16(acc[mi][ni], ahi, bhi[ni]);  // hi*hi
                mma_bf16(acc[mi][ni], alo, bhi[ni]);  // lo*hi
                mma_bf16(acc[mi][ni], ahi, blo[ni]);  // hi*lo
            }
        }

        buf = (buf + 1) & 3;
    }

    #pragma unroll
    for (int mi = 0; mi < 4; ++mi) {
        const int r = wm * 64 + mi * 16 + g;
        #pragma unroll
        for (int ni = 0; ni < 4; ++ni) {
            const int cn = wn * 32 + ni * 8 + tg * 2;
            float2 v0 = make_float2(acc[mi][ni][0], acc[mi][ni][1]);
            float2 v1 = make_float2(acc[mi][ni][2], acc[mi][ni][3]);
            *(float2*)(C + (size_t)r * ldc + cn)       = v0;
            *(float2*)(C + (size_t)(r + 8) * ldc + cn) = v1;
        }
    }
}

// ---------------------------------------------------------------------------
// GEMV: out[r] = dot(Mtx[r, 0:1024], vec), one warp per row.
// ---------------------------------------------------------------------------
__global__ void __launch_bounds__(256)
gemv1024(const float* __restrict__ Mtx, const float* __restrict__ vec,
         float* __restrict__ out, int rows)
{
    const int w    = threadIdx.x >> 5;
    const int lane = threadIdx.x & 31;
    const int r    = blockIdx.x * 8 + w;
    if (r >= rows) return;

    const float4* row = (const float4*)(Mtx + (size_t)r * HID);
    const float4* v4  = (const float4*)vec;
    float s = 0.f;
    #pragma unroll
    for (int i = 0; i < 8; ++i) {
        float4 a = row[lane + 32 * i];
        float4 b = v4[lane + 32 * i];
        s += a.x * b.x + a.y * b.y + a.z * b.z + a.w * b.w;
    }
    #pragma unroll
    for (int o = 16; o; o >>= 1) s += __shfl_xor_sync(0xffffffffu, s, o);
    if (lane == 0) out[r] = s;
}

// ---------------------------------------------------------------------------
// Softmax over rows of S [pairs,256,512] in place + column-sum into scores.
// ---------------------------------------------------------------------------
__global__ void __launch_bounds__(256)
softmax_scores(float* __restrict__ S, float* __restrict__ scores)
{
    const int pair = blockIdx.y;
    const int w    = threadIdx.x >> 5;
    const int lane = threadIdx.x & 31;

    __shared__ float colsum[SEQK];
    for (int i = threadIdx.x; i < SEQK; i += 256) colsum[i] = 0.f;
    __syncthreads();

    float* row = S + (size_t)pair * SEQQ * SEQK + (size_t)(blockIdx.x * 8 + w) * SEQK;

    float v[16];
    #pragma unroll
    for (int i = 0; i < 16; ++i) v[i] = row[lane + 32 * i];

    float m = v[0];
    #pragma unroll
    for (int i = 1; i < 16; ++i) m = fmaxf(m, v[i]);
    #pragma unroll
    for (int o = 16; o; o >>= 1) m = fmaxf(m, __shfl_xor_sync(0xffffffffu, m, o));

    float s = 0.f;
    #pragma unroll
    for (int i = 0; i < 16; ++i) { v[i] = __expf(v[i] - m); s += v[i]; }
    #pragma unroll
    for (int o = 16; o; o >>= 1) s += __shfl_xor_sync(0xffffffffu, s, o);

    const float inv = 1.f / s;
    #pragma unroll
    for (int i = 0; i < 16; ++i) {
        const float p = v[i] * inv;
        row[lane + 32 * i] = p;
        atomicAdd(&colsum[lane + 32 * i], p);
    }
    __syncthreads();
    for (int i = threadIdx.x; i < SEQK; i += 256)
        atomicAdd(&scores[(size_t)pair * SEQK + i], colsum[i]);
}

// ---------------------------------------------------------------------------
// kernel_launch
// inputs: query, source, Wq, bq, Wk, bk, Wv, bv
// output: context [8,32,256,1024] then attention_scores [8,32,512]
// ---------------------------------------------------------------------------
extern "C" void kernel_launch(void* const* d_in, const int* in_sizes, int n_in,
                              void* d_out, int out_size)
{
    const float* query  = (const float*)d_in[0];
    const float* source = (const float*)d_in[1];
    const float* Wq = (const float*)d_in[2];
    const float* bq = (const float*)d_in[3];
    const float* Wk = (const float*)d_in[4];
    // bk unused: its logits contribution is constant per softmax row.
    const float* Wv = (const float*)d_in[6];
    const float* bv = (const float*)d_in[7];

    float* ctx    = (float*)d_out;
    float* scores = ctx + (size_t)PAIRS * SEQQ * HID;

    float *M, *A, *S, *Y, *v, *w2;
    cudaGetSymbolAddress((void**)&M,  g_M);
    cudaGetSymbolAddress((void**)&A,  g_A);
    cudaGetSymbolAddress((void**)&S,  g_S);
    cudaGetSymbolAddress((void**)&Y,  g_Y);
    cudaGetSymbolAddress((void**)&v,  g_v);
    cudaGetSymbolAddress((void**)&w2, g_w2);

    const int SM_T = 4 * (128 * 20 + 128 * 20) * 4;   // 81920 B (TRANSB)
    const int SM_N = 4 * (128 * 20 + 16 * 136) * 4;   // 75776 B

    cudaFuncSetAttribute(gemm3x<true,  false, false, 3>, cudaFuncAttributeMaxDynamicSharedMemorySize, SM_T);
    cudaFuncSetAttribute(gemm3x<true,  true,  true,  3>, cudaFuncAttributeMaxDynamicSharedMemorySize, SM_T);
    cudaFuncSetAttribute(gemm3x<false, false, false, 2>, cudaFuncAttributeMaxDynamicSharedMemorySize, SM_N);
    cudaFuncSetAttribute(gemm3x<false, true,  false, 2>, cudaFuncAttributeMaxDynamicSharedMemorySize, SM_N);
    cudaFuncSetAttribute(gemmbf, cudaFuncAttributeMaxDynamicSharedMemorySize, SM_N);

    cudaMemsetAsync(scores, 0, (size_t)PAIRS * SEQK * sizeof(float));

    dim3 blk(256);

    // w2 = Wk * bq  (row-dot), then v = Xs * w2 per (pair, s)
    gemv1024<<<HID / 8, 256>>>(Wk, bq, w2, HID);
    gemv1024<<<MS / 8, 256>>>(source, w2, v, MS);

    // M = Wq * Wk^T  [1024,1024]  (tf32 3-pass: feeds logits)
    gemm3x<true, false, false, 3><<<dim3(HID / 128, HID / 128, 1), blk, SM_T>>>(
        Wq, Wk, nullptr, M, HID, HID, HID, HID, 0, 0, 0);

    // A = Xq * M  [65536,1024]  (bf16 3-pass, 2x MAC rate)
    gemmbf<<<dim3(HID / 128, MQ / 128, 1), blk, SM_N>>>(
        query, M, A, HID, HID, HID, HID);

    // logits S = A * Xs^T + v[pair, s]  (tf32 3-pass; batched over pairs)
    gemm3x<true, true, true, 3><<<dim3(SEQK / 128, SEQQ / 128, PAIRS), blk, SM_T>>>(
        A, source, v, S, HID, HID, HID, SEQK,
        (size_t)SEQQ * HID, (size_t)SEQK * HID, (size_t)SEQQ * SEQK);

    // softmax (in place -> P) + scores
    softmax_scores<<<dim3(SEQQ / 8, PAIRS), 256>>>(S, scores);

    // Y = P * Xs  (tf32 2-pass post-softmax; batched)
    gemm3x<false, false, false, 2><<<dim3(HID / 128, SEQQ / 128, PAIRS), blk, SM_N>>>(
        S, source, nullptr, Y, SEQK, SEQK, HID, HID,
        (size_t)SEQQ * SEQK, (size_t)SEQK * HID, (size_t)SEQQ * HID);

    // context = Y * Wv + bv  (tf32 2-pass post-softmax)
    gemm3x<false, true, false, 2><<<dim3(HID / 128, MQ / 128, 1), blk, SM_N>>>(
        Y, Wv, bv, ctx, HID, HID, HID, HID, 0, 0, 0);
}